// round 6
// baseline (speedup 1.0000x reference)
#include <cuda_runtime.h>
#include <cuda_bf16.h>
#include <math.h>
#include <stdint.h>

#define BATCH 4
#define SEQ   2048
#define HID   256
#define NTOK  (BATCH*SEQ)   // 8192
#define NHEAD 8
#define DPH   32
#define WINSZ 64
#define NWIN  32

typedef __nv_bfloat16 bf16;

// ---------------- scratch (no allocs allowed) ----------------
__device__ float g_q[NTOK*HID];
__device__ float g_k[NTOK*HID];
__device__ float g_v[NTOK*HID];
__device__ float g_pe[NTOK*HID];

__device__ bf16 g_ah[NTOK*HID],   g_al[NTOK*HID];     // inputs split
__device__ bf16 g_pe1h[NTOK*HID], g_pe1l[NTOK*HID];   // pos-mlp stage1 split
__device__ bf16 g_ctxh[NTOK*HID], g_ctxl[NTOK*HID];   // attn output split
__device__ bf16 g_wh[5*HID*HID],  g_wl[5*HID*HID];    // 5 weights TRANSPOSED [n][k], split

__device__ float g_A2[HID], g_B2[HID], g_C2[HID];     // centered pos1 weights * ln_g
__device__ float g_pstat[6];                          // Saa,Sbb,Sab,Sac,Sbc,Scc

__device__ __forceinline__ float gelu_exact(float x) {
    return 0.5f * x * (1.0f + erff(x * 0.70710678118654752f));
}
__device__ __forceinline__ uint32_t pkbf(float a, float b) {
    return (uint32_t)__bfloat16_as_ushort(__float2bfloat16(a)) |
           ((uint32_t)__bfloat16_as_ushort(__float2bfloat16(b)) << 16);
}
__device__ __forceinline__ float bfv(uint32_t p, int hi) {
    return __bfloat162float(__ushort_as_bfloat16((unsigned short)(hi ? (p >> 16) : p)));
}

__device__ __forceinline__ void ldsm4(uint32_t* r, const void* p) {
    uint32_t a = (uint32_t)__cvta_generic_to_shared(p);
    asm volatile("ldmatrix.sync.aligned.m8n8.x4.shared.b16 {%0,%1,%2,%3}, [%4];"
                 : "=r"(r[0]), "=r"(r[1]), "=r"(r[2]), "=r"(r[3]) : "r"(a));
}
__device__ __forceinline__ void mma_bf16(float* d, const uint32_t* a,
                                         uint32_t b0, uint32_t b1) {
    asm volatile(
        "mma.sync.aligned.m16n8k16.row.col.f32.bf16.bf16.f32 "
        "{%0,%1,%2,%3}, {%4,%5,%6,%7}, {%8,%9}, {%0,%1,%2,%3};\n"
        : "+f"(d[0]), "+f"(d[1]), "+f"(d[2]), "+f"(d[3])
        : "r"(a[0]), "r"(a[1]), "r"(a[2]), "r"(a[3]), "r"(b0), "r"(b1));
}
__device__ __forceinline__ void cpa16(uint32_t s, const void* g) {
    asm volatile("cp.async.cg.shared.global [%0], [%1], 16;" :: "r"(s), "l"(g));
}
__device__ __forceinline__ void cpa_commit() {
    asm volatile("cp.async.commit_group;");
}
__device__ __forceinline__ void cpa_wait1() {
    asm volatile("cp.async.wait_group 1;");
}

// ================= prep kernels =================
// split+TRANSPOSE the 5 weights: g_wh[w][n*256+k] = bf16split(W[k*256+n])
__global__ __launch_bounds__(256) void prep_w(
    const float* __restrict__ wq, const float* __restrict__ wk,
    const float* __restrict__ wv, const float* __restrict__ p2w,
    const float* __restrict__ wo)
{
    __shared__ float t[64][65];
    const int w = blockIdx.x;
    const float* src = (w == 0) ? wq : (w == 1) ? wk : (w == 2) ? wv :
                       (w == 3) ? p2w : wo;
    const int n0 = (blockIdx.y & 3) * 64, k0 = (blockIdx.y >> 2) * 64;
    const int tid = threadIdx.x;
#pragma unroll
    for (int i = 0; i < 4; i++) {
        int f = i * 256 + tid;
        int kr = f >> 4, nc = (f & 15) * 4;
        float4 v = *(const float4*)(src + (size_t)(k0 + kr) * 256 + n0 + nc);
        t[kr][nc] = v.x; t[kr][nc+1] = v.y; t[kr][nc+2] = v.z; t[kr][nc+3] = v.w;
    }
    __syncthreads();
#pragma unroll
    for (int i = 0; i < 4; i++) {
        int f = i * 256 + tid;
        int nr = f >> 4, kc = (f & 15) * 4;
        float a = t[kc][nr], b = t[kc+1][nr], c = t[kc+2][nr], d = t[kc+3][nr];
        uint32_t h01 = pkbf(a, b), h23 = pkbf(c, d);
        size_t o = (size_t)w * 65536 + (size_t)(n0 + nr) * 256 + k0 + kc;
        *(uint32_t*)(&g_wh[o])     = h01;
        *(uint32_t*)(&g_wh[o + 2]) = h23;
        *(uint32_t*)(&g_wl[o])     = pkbf(a - bfv(h01,0), b - bfv(h01,1));
        *(uint32_t*)(&g_wl[o + 2]) = pkbf(c - bfv(h23,0), d - bfv(h23,1));
    }
}

__global__ __launch_bounds__(256) void prep_a(const float* __restrict__ A)
{
    const int idx = (blockIdx.x * 256 + threadIdx.x) * 4;
    float4 v = *(const float4*)(A + idx);
    uint32_t h01 = pkbf(v.x, v.y), h23 = pkbf(v.z, v.w);
    *(uint32_t*)(&g_ah[idx])     = h01;
    *(uint32_t*)(&g_ah[idx + 2]) = h23;
    *(uint32_t*)(&g_al[idx])     = pkbf(v.x - bfv(h01,0), v.y - bfv(h01,1));
    *(uint32_t*)(&g_al[idx + 2]) = pkbf(v.z - bfv(h23,0), v.w - bfv(h23,1));
}

__global__ __launch_bounds__(256) void pstat_k(
    const float* __restrict__ p1w, const float* __restrict__ p1b,
    const float* __restrict__ lng)
{
    __shared__ float red[8];
    const int t = threadIdx.x;
    const int lane = t & 31, warp = t >> 5;
    float w0 = p1w[t], w1 = p1w[256 + t], b0 = p1b[t];

    float sums[3] = {w0, w1, b0};
    float means[3];
#pragma unroll
    for (int s = 0; s < 3; s++) {
        float v = sums[s];
#pragma unroll
        for (int o = 16; o; o >>= 1) v += __shfl_xor_sync(0xffffffffu, v, o);
        if (lane == 0) red[warp] = v;
        __syncthreads();
        float tot = 0.f;
#pragma unroll
        for (int i = 0; i < 8; i++) tot += red[i];
        means[s] = tot * (1.f / 256.f);
        __syncthreads();
    }
    float a = w0 - means[0], b = w1 - means[1], c = b0 - means[2];
    float g = lng[t];
    g_A2[t] = a * g; g_B2[t] = b * g; g_C2[t] = c * g;

    float prods[6] = {a*a, b*b, a*b, a*c, b*c, c*c};
#pragma unroll
    for (int s = 0; s < 6; s++) {
        float v = prods[s];
#pragma unroll
        for (int o = 16; o; o >>= 1) v += __shfl_xor_sync(0xffffffffu, v, o);
        if (lane == 0) red[warp] = v;
        __syncthreads();
        if (t == 0) {
            float tot = 0.f;
#pragma unroll
            for (int i = 0; i < 8; i++) tot += red[i];
            g_pstat[s] = tot * (1.f / 256.f);
        }
        __syncthreads();
    }
}

// pos1: fully elementwise (reduction-free), 64 threads per token
__global__ __launch_bounds__(256) void pos1_k(
    const float* __restrict__ p, const float* __restrict__ lnb)
{
    const int idx = blockIdx.x * 256 + threadIdx.x;
    const int tok = idx >> 6;
    const int n0 = (idx & 63) * 4;
    const float p0 = p[tok * 2 + 0];
    const float p1 = p[tok * 2 + 1];
    const float var = p0*p0*g_pstat[0] + p1*p1*g_pstat[1] + 2.f*p0*p1*g_pstat[2]
                    + 2.f*p0*g_pstat[3] + 2.f*p1*g_pstat[4] + g_pstat[5];
    const float rstd = rsqrtf(var + 1e-6f);

    float4 a4 = *(const float4*)(g_A2 + n0);
    float4 b4 = *(const float4*)(g_B2 + n0);
    float4 c4 = *(const float4*)(g_C2 + n0);
    float4 bb = *(const float4*)(lnb + n0);
    float y0 = gelu_exact((p0*a4.x + p1*b4.x + c4.x) * rstd + bb.x);
    float y1 = gelu_exact((p0*a4.y + p1*b4.y + c4.y) * rstd + bb.y);
    float y2 = gelu_exact((p0*a4.z + p1*b4.z + c4.z) * rstd + bb.z);
    float y3 = gelu_exact((p0*a4.w + p1*b4.w + c4.w) * rstd + bb.w);

    const size_t o = (size_t)tok * 256 + n0;
    uint2 hh, ll;
    hh.x = pkbf(y0, y1); hh.y = pkbf(y2, y3);
    ll.x = pkbf(y0 - bfv(hh.x,0), y1 - bfv(hh.x,1));
    ll.y = pkbf(y2 - bfv(hh.y,0), y3 - bfv(hh.y,1));
    *(uint2*)(&g_pe1h[o]) = hh;
    *(uint2*)(&g_pe1l[o]) = ll;
}

// ================= pipelined mma.sync GEMM =================
// C[8192,256] = act(scale*(A@Wt^T + bias)); A[m][k] bf16 split, W [n][k] bf16 split.
// BM=128, BN=128, BK=32, 3-stage cp.async pipeline, 8 warps, warp tile 64x32.
#define STG_SZ 40960                 // 4 arrays x 128 rows x 80B
#define OA_H 0
#define OA_L 10240
#define OB_H 20480
#define OB_L 30720
#define GSMEM (3*STG_SZ)             // 122880 B

extern __shared__ char dsm[];

__device__ __forceinline__ void tile_loads(
    const bf16* Ah, const bf16* Al, const bf16* Wh, const bf16* Wl,
    int m0, int n0, int kt, int st, uint32_t smem_u32, int tid)
{
    const uint32_t sb = smem_u32 + st * STG_SZ;
#pragma unroll
    for (int i = 0; i < 2; i++) {
        int f = i * 256 + tid;
        int row = f >> 2, ch = f & 3;
        const size_t gka = (size_t)(m0 + row) * 256 + kt * 32 + ch * 8;
        const size_t gkb = (size_t)(n0 + row) * 256 + kt * 32 + ch * 8;
        const uint32_t so = row * 80 + ch * 16;
        cpa16(sb + OA_H + so, Ah + gka);
        cpa16(sb + OA_L + so, Al + gka);
        cpa16(sb + OB_H + so, Wh + gkb);
        cpa16(sb + OB_L + so, Wl + gkb);
    }
}

__device__ __forceinline__ void gemm_core(
    const bf16* __restrict__ Ah, const bf16* __restrict__ Al,
    const bf16* __restrict__ Wh, const bf16* __restrict__ Wl,
    const float* __restrict__ bias, float* __restrict__ C,
    float scale, int act, int bx, int by)
{
    const int tid  = threadIdx.x;
    const int wid  = tid >> 5;
    const int lane = tid & 31;
    const int g = lane >> 2;
    const int q = lane & 3;
    const int wm = (wid & 1) * 64;     // 2 m-warps
    const int wn = (wid >> 1) * 32;    // 4 n-warps
    const int m0 = bx * 128;
    const int n0 = by * 128;
    const uint32_t smem_u32 = (uint32_t)__cvta_generic_to_shared(dsm);

    float acc[4][4][4];
#pragma unroll
    for (int mt = 0; mt < 4; mt++)
#pragma unroll
        for (int nt = 0; nt < 4; nt++)
#pragma unroll
            for (int i = 0; i < 4; i++) acc[mt][nt][i] = 0.f;

    tile_loads(Ah, Al, Wh, Wl, m0, n0, 0, 0, smem_u32, tid);
    cpa_commit();
    tile_loads(Ah, Al, Wh, Wl, m0, n0, 1, 1, smem_u32, tid);
    cpa_commit();

    const int la = lane & 15;
    const int khalf = (lane >> 4) * 16;   // byte offset of k8 half

    for (int it = 0; it < 8; it++) {
        cpa_wait1();
        __syncthreads();
        if (it + 2 < 8)
            tile_loads(Ah, Al, Wh, Wl, m0, n0, it + 2, (it + 2) % 3, smem_u32, tid);
        cpa_commit();

        const char* sb = dsm + (it % 3) * STG_SZ;
#pragma unroll
        for (int ks = 0; ks < 2; ks++) {
            const int kb = ks * 32 + khalf;
            uint32_t ah[4][4], al[4][4], bh[2][4], bl[2][4];
#pragma unroll
            for (int mt = 0; mt < 4; mt++) {
                const char* pa = sb + (wm + mt * 16 + la) * 80 + kb;
                ldsm4(ah[mt], pa + OA_H);
                ldsm4(al[mt], pa + OA_L);
            }
#pragma unroll
            for (int np = 0; np < 2; np++) {
                const char* pb = sb + (wn + np * 16 + la) * 80 + kb;
                ldsm4(bh[np], pb + OB_H);
                ldsm4(bl[np], pb + OB_L);
            }
#pragma unroll
            for (int mt = 0; mt < 4; mt++)
#pragma unroll
                for (int nt = 0; nt < 4; nt++) {
                    const int np = nt >> 1, j = nt & 1;
                    mma_bf16(acc[mt][nt], ah[mt], bh[np][j], bh[np][j + 2]);
                    mma_bf16(acc[mt][nt], ah[mt], bl[np][j], bl[np][j + 2]);
                    mma_bf16(acc[mt][nt], al[mt], bh[np][j], bh[np][j + 2]);
                }
        }
        __syncthreads();
    }

    // epilogue: accumulators already in registers
#pragma unroll
    for (int mt = 0; mt < 4; mt++) {
        int r0 = m0 + wm + mt * 16 + g;
#pragma unroll
        for (int nt = 0; nt < 4; nt++) {
            int cn = n0 + wn + nt * 8 + 2 * q;
            float2 b2 = *(const float2*)(bias + cn);
            float v0 = (acc[mt][nt][0] + b2.x) * scale;
            float v1 = (acc[mt][nt][1] + b2.y) * scale;
            float v2 = (acc[mt][nt][2] + b2.x) * scale;
            float v3 = (acc[mt][nt][3] + b2.y) * scale;
            if (act) {
                v0 = gelu_exact(v0); v1 = gelu_exact(v1);
                v2 = gelu_exact(v2); v3 = gelu_exact(v3);
            }
            *(float2*)(C + (size_t)r0 * 256 + cn)       = make_float2(v0, v1);
            *(float2*)(C + (size_t)(r0 + 8) * 256 + cn) = make_float2(v2, v3);
        }
    }
}

__global__ __launch_bounds__(256, 1) void gemm_qkv(
    const float* __restrict__ bq, const float* __restrict__ bk,
    const float* __restrict__ bv)
{
    const int z = blockIdx.z;
    const float* bias = (z == 0) ? bq : (z == 1) ? bk : bv;
    float* C = (z == 0) ? g_q : (z == 1) ? g_k : g_v;
    float scale = (z == 0) ? 0.17677669529663689f : 1.f;
    gemm_core(g_ah, g_al, g_wh + (size_t)z * 65536, g_wl + (size_t)z * 65536,
              bias, C, scale, 0, blockIdx.x, blockIdx.y);
}
__global__ __launch_bounds__(256, 1) void gemm_pe(const float* __restrict__ p2b)
{
    gemm_core(g_pe1h, g_pe1l, g_wh + (size_t)3 * 65536, g_wl + (size_t)3 * 65536,
              p2b, g_pe, 1.f, 1, blockIdx.x, blockIdx.y);
}
__global__ __launch_bounds__(256, 1) void gemm_out(const float* __restrict__ bo,
                                                   float* __restrict__ out)
{
    gemm_core(g_ctxh, g_ctxl, g_wh + (size_t)4 * 65536, g_wl + (size_t)4 * 65536,
              bo, out, 1.f, 0, blockIdx.x, blockIdx.y);
}

// ================= windowed attention =================
// S[i,j] = q_i·(k_j - pe_j) + (c·k_j - d·pe_j) + (q_i + d)·pe_i
__global__ __launch_bounds__(256) void attn_k(
    const float* __restrict__ cvec, const float* __restrict__ dvec)
{
    const int w = blockIdx.x, h = blockIdx.y, b = blockIdx.z;

    __shared__ float sq[64][36];
    __shared__ float skw[64][36];
    __shared__ float sv[64][36];
    __shared__ float sbias[64];
    __shared__ float su[64];
    __shared__ float P[64][65];

    const int t = threadIdx.x;
    const int tok = t >> 2;
    const int l = t & 3;
    const int dl = l * 8;

    const int s = w * 64 + tok;
    const int o = s >> 4, r = s & 15;
    const int ic = ((o & 63) << 1) + (o >> 6);
    const int orig = ic * 16 + r;
    const size_t base = ((size_t)(b * SEQ + orig)) * 256 + h * 32 + dl;

    const float* cp = cvec + h * 32 + dl;
    const float* dp = dvec + h * 32 + dl;

    float bias_p = 0.f, u_p = 0.f;
#pragma unroll
    for (int i = 0; i < 8; i += 4) {
        float4 xq = *(const float4*)(g_q + base + i);
        float4 xk = *(const float4*)(g_k + base + i);
        float4 xv = *(const float4*)(g_v + base + i);
        float4 xp = *(const float4*)(g_pe + base + i);
        float4 xc = *(const float4*)(cp + i);
        float4 xd = *(const float4*)(dp + i);
        *(float4*)(&sq[tok][dl + i]) = xq;
        *(float4*)(&sv[tok][dl + i]) = xv;
        float4 kw = make_float4(xk.x - xp.x, xk.y - xp.y, xk.z - xp.z, xk.w - xp.w);
        *(float4*)(&skw[tok][dl + i]) = kw;
        bias_p += xc.x * xk.x + xc.y * xk.y + xc.z * xk.z + xc.w * xk.w;
        bias_p -= xd.x * xp.x + xd.y * xp.y + xd.z * xp.z + xd.w * xp.w;
        u_p += (xq.x + xd.x) * xp.x + (xq.y + xd.y) * xp.y +
               (xq.z + xd.z) * xp.z + (xq.w + xd.w) * xp.w;
    }
    bias_p += __shfl_xor_sync(0xffffffffu, bias_p, 1);
    bias_p += __shfl_xor_sync(0xffffffffu, bias_p, 2);
    u_p += __shfl_xor_sync(0xffffffffu, u_p, 1);
    u_p += __shfl_xor_sync(0xffffffffu, u_p, 2);
    if (l == 0) { sbias[tok] = bias_p; su[tok] = u_p; }
    __syncthreads();

    const int row = tok;
    float qrow[32];
#pragma unroll
    for (int d = 0; d < 32; d += 4) {
        float4 x = *(const float4*)(&sq[row][d]);
        qrow[d] = x.x; qrow[d + 1] = x.y; qrow[d + 2] = x.z; qrow[d + 3] = x.w;
    }
    const float urow = su[row];
    float sc[16];
    float smax = -1e30f;
#pragma unroll
    for (int jj = 0; jj < 16; jj++) {
        int j = l + (jj << 2);
        float sv2 = urow + sbias[j];
#pragma unroll
        for (int d = 0; d < 32; d += 4) {
            float4 kv = *(const float4*)(&skw[j][d]);
            sv2 += qrow[d] * kv.x + qrow[d + 1] * kv.y +
                   qrow[d + 2] * kv.z + qrow[d + 3] * kv.w;
        }
        sc[jj] = sv2;
        smax = fmaxf(smax, sv2);
    }
    smax = fmaxf(smax, __shfl_xor_sync(0xffffffffu, smax, 1));
    smax = fmaxf(smax, __shfl_xor_sync(0xffffffffu, smax, 2));
    float ssum = 0.f;
#pragma unroll
    for (int jj = 0; jj < 16; jj++) {
        sc[jj] = __expf(sc[jj] - smax);
        ssum += sc[jj];
    }
    ssum += __shfl_xor_sync(0xffffffffu, ssum, 1);
    ssum += __shfl_xor_sync(0xffffffffu, ssum, 2);
    const float inv = 1.f / ssum;
#pragma unroll
    for (int jj = 0; jj < 16; jj++) P[row][l + (jj << 2)] = sc[jj] * inv;
    __syncthreads();

    float oa[8];
#pragma unroll
    for (int i = 0; i < 8; i++) oa[i] = 0.f;
#pragma unroll
    for (int j = 0; j < 64; j++) {
        float pv = P[row][j];
        float4 v0 = *(const float4*)(&sv[j][dl]);
        float4 v1 = *(const float4*)(&sv[j][dl + 4]);
        oa[0] += pv * v0.x; oa[1] += pv * v0.y; oa[2] += pv * v0.z; oa[3] += pv * v0.w;
        oa[4] += pv * v1.x; oa[5] += pv * v1.y; oa[6] += pv * v1.z; oa[7] += pv * v1.w;
    }
    uint2 hh, ll;
    hh.x = pkbf(oa[0], oa[1]); hh.y = pkbf(oa[2], oa[3]);
    ll.x = pkbf(oa[0]-bfv(hh.x,0), oa[1]-bfv(hh.x,1));
    ll.y = pkbf(oa[2]-bfv(hh.y,0), oa[3]-bfv(hh.y,1));
    *(uint2*)(&g_ctxh[base]) = hh;
    *(uint2*)(&g_ctxl[base]) = ll;
    hh.x = pkbf(oa[4], oa[5]); hh.y = pkbf(oa[6], oa[7]);
    ll.x = pkbf(oa[4]-bfv(hh.x,0), oa[5]-bfv(hh.x,1));
    ll.y = pkbf(oa[6]-bfv(hh.y,0), oa[7]-bfv(hh.y,1));
    *(uint2*)(&g_ctxh[base + 4]) = hh;
    *(uint2*)(&g_ctxl[base + 4]) = ll;
}

// ================= launch =================
extern "C" void kernel_launch(void* const* d_in, const int* in_sizes, int n_in,
                              void* d_out, int out_size)
{
    const float* inputs = (const float*)d_in[0];
    const float* p      = (const float*)d_in[1];
    const float* wq     = (const float*)d_in[2];
    const float* bq     = (const float*)d_in[3];
    const float* wk     = (const float*)d_in[4];
    const float* bk     = (const float*)d_in[5];
    const float* wv     = (const float*)d_in[6];
    const float* bv     = (const float*)d_in[7];
    const float* wo     = (const float*)d_in[8];
    const float* bo     = (const float*)d_in[9];
    const float* p1w    = (const float*)d_in[10];
    const float* p1b    = (const float*)d_in[11];
    const float* p2w    = (const float*)d_in[12];
    const float* p2b    = (const float*)d_in[13];
    const float* lng    = (const float*)d_in[14];
    const float* lnb    = (const float*)d_in[15];
    const float* cv     = (const float*)d_in[16];
    const float* dv     = (const float*)d_in[17];
    float* out = (float*)d_out;

    cudaFuncSetAttribute(gemm_qkv, cudaFuncAttributeMaxDynamicSharedMemorySize, GSMEM);
    cudaFuncSetAttribute(gemm_pe,  cudaFuncAttributeMaxDynamicSharedMemorySize, GSMEM);
    cudaFuncSetAttribute(gemm_out, cudaFuncAttributeMaxDynamicSharedMemorySize, GSMEM);

    prep_w<<<dim3(5, 16), 256>>>(wq, wk, wv, p2w, wo);
    prep_a<<<NTOK * HID / 1024, 256>>>(inputs);
    pstat_k<<<1, 256>>>(p1w, p1b, lng);
    pos1_k<<<NTOK * 64 / 256, 256>>>(p, lnb);
    gemm_qkv<<<dim3(64, 2, 3), 256, GSMEM>>>(bq, bk, bv);
    gemm_pe<<<dim3(64, 2), 256, GSMEM>>>(p2b);
    attn_k<<<dim3(NWIN, NHEAD, BATCH), 256>>>(cv, dv);
    gemm_out<<<dim3(64, 2), 256, GSMEM>>>(bo, out);
}

// round 7
// speedup vs baseline: 1.2641x; 1.2641x over previous
#include <cuda_runtime.h>
#include <cuda_fp16.h>
#include <math.h>
#include <stdint.h>

#define BATCH 4
#define SEQ   2048
#define HID   256
#define NTOK  (BATCH*SEQ)   // 8192
#define NHEAD 8
#define DPH   32
#define WINSZ 64
#define NWIN  32

#define WSCALE     256.0f
#define WSCALE_INV 0.00390625f

// ---------------- scratch (no allocs allowed) ----------------
__device__ float g_q[NTOK*HID];
__device__ float g_k[NTOK*HID];
__device__ float g_v[NTOK*HID];
__device__ float g_pe[NTOK*HID];

__device__ __half g_af[NTOK*HID];     // inputs fp16
__device__ __half g_pe1[NTOK*HID];    // pos-mlp stage1 fp16
__device__ __half g_ctxf[NTOK*HID];   // attn output fp16
__device__ __half g_wh[5*HID*HID];    // weights*256, TRANSPOSED [n][k], fp16 hi
__device__ __half g_wl[5*HID*HID];    // residual lo

__device__ float g_A2[HID], g_B2[HID], g_C2[HID];  // centered pos1 weights * ln_g
__device__ float g_pstat[6];                       // Saa,Sbb,Sab,Sac,Sbc,Scc

__device__ __forceinline__ float gelu_exact(float x) {
    return 0.5f * x * (1.0f + erff(x * 0.70710678118654752f));
}
__device__ __forceinline__ uint32_t pkhf(float a, float b) {
    __half2 h = __floats2half2_rn(a, b);
    return *reinterpret_cast<uint32_t*>(&h);
}

__device__ __forceinline__ void ldsm4(uint32_t* r, const void* p) {
    uint32_t a = (uint32_t)__cvta_generic_to_shared(p);
    asm volatile("ldmatrix.sync.aligned.m8n8.x4.shared.b16 {%0,%1,%2,%3}, [%4];"
                 : "=r"(r[0]), "=r"(r[1]), "=r"(r[2]), "=r"(r[3]) : "r"(a));
}
__device__ __forceinline__ void mma_f16(float* d, const uint32_t* a,
                                        uint32_t b0, uint32_t b1) {
    asm volatile(
        "mma.sync.aligned.m16n8k16.row.col.f32.f16.f16.f32 "
        "{%0,%1,%2,%3}, {%4,%5,%6,%7}, {%8,%9}, {%0,%1,%2,%3};\n"
        : "+f"(d[0]), "+f"(d[1]), "+f"(d[2]), "+f"(d[3])
        : "r"(a[0]), "r"(a[1]), "r"(a[2]), "r"(a[3]), "r"(b0), "r"(b1));
}
__device__ __forceinline__ void cpa16(uint32_t s, const void* g) {
    asm volatile("cp.async.cg.shared.global [%0], [%1], 16;" :: "r"(s), "l"(g));
}
__device__ __forceinline__ void cpa_commit() { asm volatile("cp.async.commit_group;"); }
__device__ __forceinline__ void cpa_wait1()  { asm volatile("cp.async.wait_group 1;"); }
__device__ __forceinline__ void cpa_wait0()  { asm volatile("cp.async.wait_group 0;"); }

// ================= prep kernels =================
// transpose + scale the 5 weights: g_wh[w][n*256+k] = f16(W[k][n]*256), g_wl = residual
__global__ __launch_bounds__(256) void prep_w(
    const float* __restrict__ wq, const float* __restrict__ wk,
    const float* __restrict__ wv, const float* __restrict__ p2w,
    const float* __restrict__ wo)
{
    __shared__ float t[64][65];
    const int w = blockIdx.x;
    const float* src = (w == 0) ? wq : (w == 1) ? wk : (w == 2) ? wv :
                       (w == 3) ? p2w : wo;
    const int n0 = (blockIdx.y & 3) * 64, k0 = (blockIdx.y >> 2) * 64;
    const int tid = threadIdx.x;
#pragma unroll
    for (int i = 0; i < 4; i++) {
        int f = i * 256 + tid;
        int kr = f >> 4, nc = (f & 15) * 4;
        float4 v = *(const float4*)(src + (size_t)(k0 + kr) * 256 + n0 + nc);
        t[kr][nc] = v.x; t[kr][nc+1] = v.y; t[kr][nc+2] = v.z; t[kr][nc+3] = v.w;
    }
    __syncthreads();
#pragma unroll
    for (int i = 0; i < 4; i++) {
        int f = i * 256 + tid;
        int nr = f >> 4, kc = (f & 15) * 4;
        size_t o = (size_t)w * 65536 + (size_t)(n0 + nr) * 256 + k0 + kc;
#pragma unroll
        for (int j = 0; j < 4; j++) {
            float v = t[kc + j][nr] * WSCALE;
            __half h = __float2half_rn(v);
            g_wh[o + j] = h;
            g_wl[o + j] = __float2half_rn(v - __half2float(h));
        }
    }
}

__global__ __launch_bounds__(256) void prep_a(const float* __restrict__ A)
{
    const int idx = (blockIdx.x * 256 + threadIdx.x) * 4;
    float4 v = *(const float4*)(A + idx);
    uint2 o;
    o.x = pkhf(v.x, v.y);
    o.y = pkhf(v.z, v.w);
    *(uint2*)(&g_af[idx]) = o;
}

__global__ __launch_bounds__(256) void pstat_k(
    const float* __restrict__ p1w, const float* __restrict__ p1b,
    const float* __restrict__ lng)
{
    __shared__ float red[8];
    const int t = threadIdx.x;
    const int lane = t & 31, warp = t >> 5;
    float w0 = p1w[t], w1 = p1w[256 + t], b0 = p1b[t];

    float sums[3] = {w0, w1, b0};
    float means[3];
#pragma unroll
    for (int s = 0; s < 3; s++) {
        float v = sums[s];
#pragma unroll
        for (int o = 16; o; o >>= 1) v += __shfl_xor_sync(0xffffffffu, v, o);
        if (lane == 0) red[warp] = v;
        __syncthreads();
        float tot = 0.f;
#pragma unroll
        for (int i = 0; i < 8; i++) tot += red[i];
        means[s] = tot * (1.f / 256.f);
        __syncthreads();
    }
    float a = w0 - means[0], b = w1 - means[1], c = b0 - means[2];
    float g = lng[t];
    g_A2[t] = a * g; g_B2[t] = b * g; g_C2[t] = c * g;

    float prods[6] = {a*a, b*b, a*b, a*c, b*c, c*c};
#pragma unroll
    for (int s = 0; s < 6; s++) {
        float v = prods[s];
#pragma unroll
        for (int o = 16; o; o >>= 1) v += __shfl_xor_sync(0xffffffffu, v, o);
        if (lane == 0) red[warp] = v;
        __syncthreads();
        if (t == 0) {
            float tot = 0.f;
#pragma unroll
            for (int i = 0; i < 8; i++) tot += red[i];
            g_pstat[s] = tot * (1.f / 256.f);
        }
        __syncthreads();
    }
}

// pos1: fully elementwise (reduction-free), writes fp16
__global__ __launch_bounds__(256) void pos1_k(
    const float* __restrict__ p, const float* __restrict__ lnb)
{
    const int idx = blockIdx.x * 256 + threadIdx.x;
    const int tok = idx >> 6;
    const int n0 = (idx & 63) * 4;
    const float p0 = p[tok * 2 + 0];
    const float p1 = p[tok * 2 + 1];
    const float var = p0*p0*g_pstat[0] + p1*p1*g_pstat[1] + 2.f*p0*p1*g_pstat[2]
                    + 2.f*p0*g_pstat[3] + 2.f*p1*g_pstat[4] + g_pstat[5];
    const float rstd = rsqrtf(var + 1e-6f);

    float4 a4 = *(const float4*)(g_A2 + n0);
    float4 b4 = *(const float4*)(g_B2 + n0);
    float4 c4 = *(const float4*)(g_C2 + n0);
    float4 bb = *(const float4*)(lnb + n0);
    float y0 = gelu_exact((p0*a4.x + p1*b4.x + c4.x) * rstd + bb.x);
    float y1 = gelu_exact((p0*a4.y + p1*b4.y + c4.y) * rstd + bb.y);
    float y2 = gelu_exact((p0*a4.z + p1*b4.z + c4.z) * rstd + bb.z);
    float y3 = gelu_exact((p0*a4.w + p1*b4.w + c4.w) * rstd + bb.w);

    uint2 o;
    o.x = pkhf(y0, y1);
    o.y = pkhf(y2, y3);
    *(uint2*)(&g_pe1[(size_t)tok * 256 + n0]) = o;
}

// ================= fp16 2-term GEMM =================
// C[8192,256] = act(scale*(A@W + bias)); A fp16, W = (Wh+Wl)*2^-8 [n][k].
// BM=128, BN=128, BK=32, 2-stage cp.async, 8 warps, warp tile 64x32, occ 2.
#define OA  0
#define OWH 10240
#define OWL 20480
#define STG 30720
#define GSMEM (2*STG)   // 61440

extern __shared__ char dsm[];

__device__ __forceinline__ void tile_loads(
    const __half* Af, const __half* Wh, const __half* Wl,
    int m0, int n0, int kt, int st, uint32_t smem_u32, int tid)
{
    const uint32_t sb = smem_u32 + st * STG;
#pragma unroll
    for (int i = 0; i < 2; i++) {
        int f = i * 256 + tid;
        int row = f >> 2, ch = f & 3;
        const uint32_t so = row * 80 + ch * 16;
        const size_t gka = (size_t)(m0 + row) * 256 + kt * 32 + ch * 8;
        const size_t gkb = (size_t)(n0 + row) * 256 + kt * 32 + ch * 8;
        cpa16(sb + OA + so,  Af + gka);
        cpa16(sb + OWH + so, Wh + gkb);
        cpa16(sb + OWL + so, Wl + gkb);
    }
}

__device__ __forceinline__ void gemm_core(
    const __half* __restrict__ Af,
    const __half* __restrict__ Wh, const __half* __restrict__ Wl,
    const float* __restrict__ bias, float* __restrict__ C,
    float scale, int act, int bx, int by)
{
    const int tid  = threadIdx.x;
    const int wid  = tid >> 5;
    const int lane = tid & 31;
    const int g = lane >> 2;
    const int q = lane & 3;
    const int wm = (wid & 1) * 64;     // 2 m-warps
    const int wn = (wid >> 1) * 32;    // 4 n-warps
    const int m0 = bx * 128;
    const int n0 = by * 128;
    const uint32_t smem_u32 = (uint32_t)__cvta_generic_to_shared(dsm);

    float acc[4][4][4];
#pragma unroll
    for (int mt = 0; mt < 4; mt++)
#pragma unroll
        for (int nt = 0; nt < 4; nt++)
#pragma unroll
            for (int i = 0; i < 4; i++) acc[mt][nt][i] = 0.f;

    tile_loads(Af, Wh, Wl, m0, n0, 0, 0, smem_u32, tid);
    cpa_commit();

    const int la = lane & 15;
    const int khalf = (lane >> 4) * 16;

    for (int it = 0; it < 8; it++) {
        if (it < 7) {
            tile_loads(Af, Wh, Wl, m0, n0, it + 1, (it + 1) & 1, smem_u32, tid);
            cpa_commit();
            cpa_wait1();
        } else {
            cpa_wait0();
        }
        __syncthreads();

        const char* sb = dsm + (it & 1) * STG;
#pragma unroll
        for (int ks = 0; ks < 2; ks++) {
            const int kb = ks * 32 + khalf;
            uint32_t a[4][4], bh[2][4], bl[2][4];
#pragma unroll
            for (int mt = 0; mt < 4; mt++)
                ldsm4(a[mt], sb + OA + (wm + mt * 16 + la) * 80 + kb);
#pragma unroll
            for (int np = 0; np < 2; np++) {
                ldsm4(bh[np], sb + OWH + (wn + np * 16 + la) * 80 + kb);
                ldsm4(bl[np], sb + OWL + (wn + np * 16 + la) * 80 + kb);
            }
#pragma unroll
            for (int mt = 0; mt < 4; mt++)
#pragma unroll
                for (int nt = 0; nt < 4; nt++) {
                    const int np = nt >> 1, j = nt & 1;
                    mma_f16(acc[mt][nt], a[mt], bh[np][j], bh[np][j + 2]);
                    mma_f16(acc[mt][nt], a[mt], bl[np][j], bl[np][j + 2]);
                }
        }
        __syncthreads();
    }

    // epilogue
#pragma unroll
    for (int mt = 0; mt < 4; mt++) {
        int r0 = m0 + wm + mt * 16 + g;
#pragma unroll
        for (int nt = 0; nt < 4; nt++) {
            int cn = n0 + wn + nt * 8 + 2 * q;
            float2 b2 = *(const float2*)(bias + cn);
            float v0 = (acc[mt][nt][0] * WSCALE_INV + b2.x) * scale;
            float v1 = (acc[mt][nt][1] * WSCALE_INV + b2.y) * scale;
            float v2 = (acc[mt][nt][2] * WSCALE_INV + b2.x) * scale;
            float v3 = (acc[mt][nt][3] * WSCALE_INV + b2.y) * scale;
            if (act) {
                v0 = gelu_exact(v0); v1 = gelu_exact(v1);
                v2 = gelu_exact(v2); v3 = gelu_exact(v3);
            }
            *(float2*)(C + (size_t)r0 * 256 + cn)       = make_float2(v0, v1);
            *(float2*)(C + (size_t)(r0 + 8) * 256 + cn) = make_float2(v2, v3);
        }
    }
}

__global__ __launch_bounds__(256, 2) void gemm_qkv(
    const float* __restrict__ bq, const float* __restrict__ bk,
    const float* __restrict__ bv)
{
    const int z = blockIdx.z;
    const float* bias = (z == 0) ? bq : (z == 1) ? bk : bv;
    float* C = (z == 0) ? g_q : (z == 1) ? g_k : g_v;
    float scale = (z == 0) ? 0.17677669529663689f : 1.f;
    gemm_core(g_af, g_wh + (size_t)z * 65536, g_wl + (size_t)z * 65536,
              bias, C, scale, 0, blockIdx.x, blockIdx.y);
}
__global__ __launch_bounds__(256, 2) void gemm_pe(const float* __restrict__ p2b)
{
    gemm_core(g_pe1, g_wh + (size_t)3 * 65536, g_wl + (size_t)3 * 65536,
              p2b, g_pe, 1.f, 1, blockIdx.x, blockIdx.y);
}
__global__ __launch_bounds__(256, 2) void gemm_out(const float* __restrict__ bo,
                                                   float* __restrict__ out)
{
    gemm_core(g_ctxf, g_wh + (size_t)4 * 65536, g_wl + (size_t)4 * 65536,
              bo, out, 1.f, 0, blockIdx.x, blockIdx.y);
}

// ================= windowed attention =================
// S[i,j] = q_i·(k_j - pe_j) + (c·k_j - d·pe_j) + (q_i + d)·pe_i
__global__ __launch_bounds__(256) void attn_k(
    const float* __restrict__ cvec, const float* __restrict__ dvec)
{
    const int w = blockIdx.x, h = blockIdx.y, b = blockIdx.z;

    __shared__ float sq[64][36];
    __shared__ float skw[64][36];
    __shared__ float sv[64][36];
    __shared__ float sbias[64];
    __shared__ float su[64];
    __shared__ float P[64][65];

    const int t = threadIdx.x;
    const int tok = t >> 2;
    const int l = t & 3;
    const int dl = l * 8;

    const int s = w * 64 + tok;
    const int o = s >> 4, r = s & 15;
    const int ic = ((o & 63) << 1) + (o >> 6);
    const int orig = ic * 16 + r;
    const size_t base = ((size_t)(b * SEQ + orig)) * 256 + h * 32 + dl;

    const float* cp = cvec + h * 32 + dl;
    const float* dp = dvec + h * 32 + dl;

    float bias_p = 0.f, u_p = 0.f;
#pragma unroll
    for (int i = 0; i < 8; i += 4) {
        float4 xq = *(const float4*)(g_q + base + i);
        float4 xk = *(const float4*)(g_k + base + i);
        float4 xv = *(const float4*)(g_v + base + i);
        float4 xp = *(const float4*)(g_pe + base + i);
        float4 xc = *(const float4*)(cp + i);
        float4 xd = *(const float4*)(dp + i);
        *(float4*)(&sq[tok][dl + i]) = xq;
        *(float4*)(&sv[tok][dl + i]) = xv;
        float4 kw = make_float4(xk.x - xp.x, xk.y - xp.y, xk.z - xp.z, xk.w - xp.w);
        *(float4*)(&skw[tok][dl + i]) = kw;
        bias_p += xc.x * xk.x + xc.y * xk.y + xc.z * xk.z + xc.w * xk.w;
        bias_p -= xd.x * xp.x + xd.y * xp.y + xd.z * xp.z + xd.w * xp.w;
        u_p += (xq.x + xd.x) * xp.x + (xq.y + xd.y) * xp.y +
               (xq.z + xd.z) * xp.z + (xq.w + xd.w) * xp.w;
    }
    bias_p += __shfl_xor_sync(0xffffffffu, bias_p, 1);
    bias_p += __shfl_xor_sync(0xffffffffu, bias_p, 2);
    u_p += __shfl_xor_sync(0xffffffffu, u_p, 1);
    u_p += __shfl_xor_sync(0xffffffffu, u_p, 2);
    if (l == 0) { sbias[tok] = bias_p; su[tok] = u_p; }
    __syncthreads();

    const int row = tok;
    float qrow[32];
#pragma unroll
    for (int d = 0; d < 32; d += 4) {
        float4 x = *(const float4*)(&sq[row][d]);
        qrow[d] = x.x; qrow[d + 1] = x.y; qrow[d + 2] = x.z; qrow[d + 3] = x.w;
    }
    const float urow = su[row];
    float sc[16];
    float smax = -1e30f;
#pragma unroll
    for (int jj = 0; jj < 16; jj++) {
        int j = l + (jj << 2);
        float sv2 = urow + sbias[j];
#pragma unroll
        for (int d = 0; d < 32; d += 4) {
            float4 kv = *(const float4*)(&skw[j][d]);
            sv2 += qrow[d] * kv.x + qrow[d + 1] * kv.y +
                   qrow[d + 2] * kv.z + qrow[d + 3] * kv.w;
        }
        sc[jj] = sv2;
        smax = fmaxf(smax, sv2);
    }
    smax = fmaxf(smax, __shfl_xor_sync(0xffffffffu, smax, 1));
    smax = fmaxf(smax, __shfl_xor_sync(0xffffffffu, smax, 2));
    float ssum = 0.f;
#pragma unroll
    for (int jj = 0; jj < 16; jj++) {
        sc[jj] = __expf(sc[jj] - smax);
        ssum += sc[jj];
    }
    ssum += __shfl_xor_sync(0xffffffffu, ssum, 1);
    ssum += __shfl_xor_sync(0xffffffffu, ssum, 2);
    const float inv = 1.f / ssum;
#pragma unroll
    for (int jj = 0; jj < 16; jj++) P[row][l + (jj << 2)] = sc[jj] * inv;
    __syncthreads();

    float oa[8];
#pragma unroll
    for (int i = 0; i < 8; i++) oa[i] = 0.f;
#pragma unroll
    for (int j = 0; j < 64; j++) {
        float pv = P[row][j];
        float4 v0 = *(const float4*)(&sv[j][dl]);
        float4 v1 = *(const float4*)(&sv[j][dl + 4]);
        oa[0] += pv * v0.x; oa[1] += pv * v0.y; oa[2] += pv * v0.z; oa[3] += pv * v0.w;
        oa[4] += pv * v1.x; oa[5] += pv * v1.y; oa[6] += pv * v1.z; oa[7] += pv * v1.w;
    }
    uint2 o0, o1;
    o0.x = pkhf(oa[0], oa[1]); o0.y = pkhf(oa[2], oa[3]);
    o1.x = pkhf(oa[4], oa[5]); o1.y = pkhf(oa[6], oa[7]);
    *(uint2*)(&g_ctxf[base])     = o0;
    *(uint2*)(&g_ctxf[base + 4]) = o1;
}

// ================= launch =================
extern "C" void kernel_launch(void* const* d_in, const int* in_sizes, int n_in,
                              void* d_out, int out_size)
{
    const float* inputs = (const float*)d_in[0];
    const float* p      = (const float*)d_in[1];
    const float* wq     = (const float*)d_in[2];
    const float* bq     = (const float*)d_in[3];
    const float* wk     = (const float*)d_in[4];
    const float* bk     = (const float*)d_in[5];
    const float* wv     = (const float*)d_in[6];
    const float* bv     = (const float*)d_in[7];
    const float* wo     = (const float*)d_in[8];
    const float* bo     = (const float*)d_in[9];
    const float* p1w    = (const float*)d_in[10];
    const float* p1b    = (const float*)d_in[11];
    const float* p2w    = (const float*)d_in[12];
    const float* p2b    = (const float*)d_in[13];
    const float* lng    = (const float*)d_in[14];
    const float* lnb    = (const float*)d_in[15];
    const float* cv     = (const float*)d_in[16];
    const float* dv     = (const float*)d_in[17];
    float* out = (float*)d_out;

    cudaFuncSetAttribute(gemm_qkv, cudaFuncAttributeMaxDynamicSharedMemorySize, GSMEM);
    cudaFuncSetAttribute(gemm_pe,  cudaFuncAttributeMaxDynamicSharedMemorySize, GSMEM);
    cudaFuncSetAttribute(gemm_out, cudaFuncAttributeMaxDynamicSharedMemorySize, GSMEM);

    prep_w<<<dim3(5, 16), 256>>>(wq, wk, wv, p2w, wo);
    prep_a<<<NTOK * HID / 1024, 256>>>(inputs);
    pstat_k<<<1, 256>>>(p1w, p1b, lng);
    pos1_k<<<NTOK * 64 / 256, 256>>>(p, lnb);
    gemm_qkv<<<dim3(64, 2, 3), 256, GSMEM>>>(bq, bk, bv);
    gemm_pe<<<dim3(64, 2), 256, GSMEM>>>(p2b);
    attn_k<<<dim3(NWIN, NHEAD, BATCH), 256>>>(cv, dv);
    gemm_out<<<dim3(64, 2), 256, GSMEM>>>(bo, out);
}

// round 9
// speedup vs baseline: 1.8780x; 1.4856x over previous
#include <cuda_runtime.h>
#include <cuda_fp16.h>
#include <math.h>
#include <stdint.h>

#define BATCH 4
#define SEQ   2048
#define HID   256
#define NTOK  (BATCH*SEQ)   // 8192
#define NHEAD 8
#define DPH   32
#define WINSZ 64
#define NWIN  32

#define WSCALE     256.0f
#define WSCALE_INV 0.00390625f

// ---------------- scratch (no allocs allowed) ----------------
__device__ float g_q[NTOK*HID];
__device__ float g_k[NTOK*HID];
__device__ float g_v[NTOK*HID];
__device__ float g_pe[NTOK*HID];

__device__ __half g_af[NTOK*HID];     // inputs fp16
__device__ __half g_pe1[NTOK*HID];    // pos-mlp stage1 fp16
__device__ __half g_ctxf[NTOK*HID];   // attn output fp16
__device__ __half g_wh[5*HID*HID];    // weights*256, TRANSPOSED [n][k], fp16 hi
__device__ __half g_wl[5*HID*HID];    // residual lo

__device__ float g_A2[HID], g_B2[HID], g_C2[HID];  // centered pos1 weights * ln_g
__device__ float g_pstat[6];                       // Saa,Sbb,Sab,Sac,Sbc,Scc

__device__ __forceinline__ float gelu_exact(float x) {
    return 0.5f * x * (1.0f + erff(x * 0.70710678118654752f));
}
__device__ __forceinline__ uint32_t pkhf(float a, float b) {
    __half2 h = __floats2half2_rn(a, b);
    return *reinterpret_cast<uint32_t*>(&h);
}

__device__ __forceinline__ void ldsm4(uint32_t* r, const void* p) {
    uint32_t a = (uint32_t)__cvta_generic_to_shared(p);
    asm volatile("ldmatrix.sync.aligned.m8n8.x4.shared.b16 {%0,%1,%2,%3}, [%4];"
                 : "=r"(r[0]), "=r"(r[1]), "=r"(r[2]), "=r"(r[3]) : "r"(a));
}
__device__ __forceinline__ void ldsm4t(uint32_t* r, const void* p) {
    uint32_t a = (uint32_t)__cvta_generic_to_shared(p);
    asm volatile("ldmatrix.sync.aligned.m8n8.x4.trans.shared.b16 {%0,%1,%2,%3}, [%4];"
                 : "=r"(r[0]), "=r"(r[1]), "=r"(r[2]), "=r"(r[3]) : "r"(a));
}
__device__ __forceinline__ void mma_f16(float* d, const uint32_t* a,
                                        uint32_t b0, uint32_t b1) {
    asm volatile(
        "mma.sync.aligned.m16n8k16.row.col.f32.f16.f16.f32 "
        "{%0,%1,%2,%3}, {%4,%5,%6,%7}, {%8,%9}, {%0,%1,%2,%3};\n"
        : "+f"(d[0]), "+f"(d[1]), "+f"(d[2]), "+f"(d[3])
        : "r"(a[0]), "r"(a[1]), "r"(a[2]), "r"(a[3]), "r"(b0), "r"(b1));
}
__device__ __forceinline__ void cpa16(uint32_t s, const void* g) {
    asm volatile("cp.async.cg.shared.global [%0], [%1], 16;" :: "r"(s), "l"(g));
}
__device__ __forceinline__ void cpa_commit() { asm volatile("cp.async.commit_group;"); }
__device__ __forceinline__ void cpa_wait1()  { asm volatile("cp.async.wait_group 1;"); }
__device__ __forceinline__ void cpa_wait0()  { asm volatile("cp.async.wait_group 0;"); }

// ================= fused prep: weights + inputs + pstat =================
// blocks [0,80): prep_w; [80,2128): prep_a; 2128: pstat
__global__ __launch_bounds__(256) void prep_all(
    const float* __restrict__ wq, const float* __restrict__ wk,
    const float* __restrict__ wv, const float* __restrict__ p2w,
    const float* __restrict__ wo, const float* __restrict__ A,
    const float* __restrict__ p1w, const float* __restrict__ p1b,
    const float* __restrict__ lng)
{
    __shared__ float t[64][65];
    __shared__ float red[8];
    const int bid = blockIdx.x;
    const int tid = threadIdx.x;

    if (bid < 80) {
        const int w = bid >> 4;
        const float* src = (w == 0) ? wq : (w == 1) ? wk : (w == 2) ? wv :
                           (w == 3) ? p2w : wo;
        const int y = bid & 15;
        const int n0 = (y & 3) * 64, k0 = (y >> 2) * 64;
#pragma unroll
        for (int i = 0; i < 4; i++) {
            int f = i * 256 + tid;
            int kr = f >> 4, nc = (f & 15) * 4;
            float4 v = *(const float4*)(src + (size_t)(k0 + kr) * 256 + n0 + nc);
            t[kr][nc] = v.x; t[kr][nc+1] = v.y; t[kr][nc+2] = v.z; t[kr][nc+3] = v.w;
        }
        __syncthreads();
#pragma unroll
        for (int i = 0; i < 4; i++) {
            int f = i * 256 + tid;
            int nr = f >> 4, kc = (f & 15) * 4;
            size_t o = (size_t)w * 65536 + (size_t)(n0 + nr) * 256 + k0 + kc;
#pragma unroll
            for (int j = 0; j < 4; j++) {
                float v = t[kc + j][nr] * WSCALE;
                __half h = __float2half_rn(v);
                g_wh[o + j] = h;
                g_wl[o + j] = __float2half_rn(v - __half2float(h));
            }
        }
    } else if (bid < 2128) {
        const int idx = ((bid - 80) * 256 + tid) * 4;
        float4 v = *(const float4*)(A + idx);
        uint2 o;
        o.x = pkhf(v.x, v.y);
        o.y = pkhf(v.z, v.w);
        *(uint2*)(&g_af[idx]) = o;
    } else {
        const int lane = tid & 31, warp = tid >> 5;
        float w0 = p1w[tid], w1 = p1w[256 + tid], b0 = p1b[tid];
        float sums[3] = {w0, w1, b0};
        float means[3];
#pragma unroll
        for (int s = 0; s < 3; s++) {
            float v = sums[s];
#pragma unroll
            for (int o = 16; o; o >>= 1) v += __shfl_xor_sync(0xffffffffu, v, o);
            if (lane == 0) red[warp] = v;
            __syncthreads();
            float tot = 0.f;
#pragma unroll
            for (int i = 0; i < 8; i++) tot += red[i];
            means[s] = tot * (1.f / 256.f);
            __syncthreads();
        }
        float a = w0 - means[0], b = w1 - means[1], c = b0 - means[2];
        float g = lng[tid];
        g_A2[tid] = a * g; g_B2[tid] = b * g; g_C2[tid] = c * g;

        float prods[6] = {a*a, b*b, a*b, a*c, b*c, c*c};
#pragma unroll
        for (int s = 0; s < 6; s++) {
            float v = prods[s];
#pragma unroll
            for (int o = 16; o; o >>= 1) v += __shfl_xor_sync(0xffffffffu, v, o);
            if (lane == 0) red[warp] = v;
            __syncthreads();
            if (tid == 0) {
                float tot = 0.f;
#pragma unroll
                for (int i = 0; i < 8; i++) tot += red[i];
                g_pstat[s] = tot * (1.f / 256.f);
            }
            __syncthreads();
        }
    }
}

// pos1: reduction-free, 8 values/thread, writes fp16
__global__ __launch_bounds__(256) void pos1_k(
    const float* __restrict__ p, const float* __restrict__ lnb)
{
    const int idx = blockIdx.x * 256 + threadIdx.x;
    const int tok = idx >> 5;
    const int n0 = (idx & 31) * 8;
    const float p0 = p[tok * 2 + 0];
    const float p1 = p[tok * 2 + 1];
    const float var = p0*p0*g_pstat[0] + p1*p1*g_pstat[1] + 2.f*p0*p1*g_pstat[2]
                    + 2.f*p0*g_pstat[3] + 2.f*p1*g_pstat[4] + g_pstat[5];
    const float rstd = rsqrtf(var + 1e-6f);

    float y[8];
#pragma unroll
    for (int i = 0; i < 8; i += 4) {
        float4 a4 = *(const float4*)(g_A2 + n0 + i);
        float4 b4 = *(const float4*)(g_B2 + n0 + i);
        float4 c4 = *(const float4*)(g_C2 + n0 + i);
        float4 bb = *(const float4*)(lnb + n0 + i);
        y[i+0] = gelu_exact((p0*a4.x + p1*b4.x + c4.x) * rstd + bb.x);
        y[i+1] = gelu_exact((p0*a4.y + p1*b4.y + c4.y) * rstd + bb.y);
        y[i+2] = gelu_exact((p0*a4.z + p1*b4.z + c4.z) * rstd + bb.z);
        y[i+3] = gelu_exact((p0*a4.w + p1*b4.w + c4.w) * rstd + bb.w);
    }
    uint4 o;
    o.x = pkhf(y[0], y[1]); o.y = pkhf(y[2], y[3]);
    o.z = pkhf(y[4], y[5]); o.w = pkhf(y[6], y[7]);
    *(uint4*)(&g_pe1[(size_t)tok * 256 + n0]) = o;
}

// ================= fp16 2-term GEMM =================
#define OA  0
#define OWH 10240
#define OWL 20480
#define STG 30720
#define GSMEM (2*STG)   // 61440

extern __shared__ char dsm[];

__device__ __forceinline__ void tile_loads(
    const __half* Af, const __half* Wh, const __half* Wl,
    int m0, int n0, int kt, int st, uint32_t smem_u32, int tid)
{
    const uint32_t sb = smem_u32 + st * STG;
#pragma unroll
    for (int i = 0; i < 2; i++) {
        int f = i * 256 + tid;
        int row = f >> 2, ch = f & 3;
        const uint32_t so = row * 80 + ch * 16;
        const size_t gka = (size_t)(m0 + row) * 256 + kt * 32 + ch * 8;
        const size_t gkb = (size_t)(n0 + row) * 256 + kt * 32 + ch * 8;
        cpa16(sb + OA + so,  Af + gka);
        cpa16(sb + OWH + so, Wh + gkb);
        cpa16(sb + OWL + so, Wl + gkb);
    }
}

__device__ __forceinline__ void gemm_core(
    const __half* __restrict__ Af,
    const __half* __restrict__ Wh, const __half* __restrict__ Wl,
    const float* __restrict__ bias, float* __restrict__ C,
    float scale, int act, int bx, int by)
{
    const int tid  = threadIdx.x;
    const int wid  = tid >> 5;
    const int lane = tid & 31;
    const int g = lane >> 2;
    const int q = lane & 3;
    const int wm = (wid & 1) * 64;
    const int wn = (wid >> 1) * 32;
    const int m0 = bx * 128;
    const int n0 = by * 128;
    const uint32_t smem_u32 = (uint32_t)__cvta_generic_to_shared(dsm);

    float acc[4][4][4];
#pragma unroll
    for (int mt = 0; mt < 4; mt++)
#pragma unroll
        for (int nt = 0; nt < 4; nt++)
#pragma unroll
            for (int i = 0; i < 4; i++) acc[mt][nt][i] = 0.f;

    tile_loads(Af, Wh, Wl, m0, n0, 0, 0, smem_u32, tid);
    cpa_commit();

    const int la = lane & 15;
    const int khalf = (lane >> 4) * 16;

    for (int it = 0; it < 8; it++) {
        if (it < 7) {
            tile_loads(Af, Wh, Wl, m0, n0, it + 1, (it + 1) & 1, smem_u32, tid);
            cpa_commit();
            cpa_wait1();
        } else {
            cpa_wait0();
        }
        __syncthreads();

        const char* sb = dsm + (it & 1) * STG;
#pragma unroll
        for (int ks = 0; ks < 2; ks++) {
            const int kb = ks * 32 + khalf;
            uint32_t a[4][4], bh[2][4], bl[2][4];
#pragma unroll
            for (int mt = 0; mt < 4; mt++)
                ldsm4(a[mt], sb + OA + (wm + mt * 16 + la) * 80 + kb);
#pragma unroll
            for (int np = 0; np < 2; np++) {
                ldsm4(bh[np], sb + OWH + (wn + np * 16 + la) * 80 + kb);
                ldsm4(bl[np], sb + OWL + (wn + np * 16 + la) * 80 + kb);
            }
#pragma unroll
            for (int mt = 0; mt < 4; mt++)
#pragma unroll
                for (int nt = 0; nt < 4; nt++) {
                    const int np = nt >> 1, j = nt & 1;
                    mma_f16(acc[mt][nt], a[mt], bh[np][j], bh[np][j + 2]);
                    mma_f16(acc[mt][nt], a[mt], bl[np][j], bl[np][j + 2]);
                }
        }
        __syncthreads();
    }

#pragma unroll
    for (int mt = 0; mt < 4; mt++) {
        int r0 = m0 + wm + mt * 16 + g;
#pragma unroll
        for (int nt = 0; nt < 4; nt++) {
            int cn = n0 + wn + nt * 8 + 2 * q;
            float2 b2 = *(const float2*)(bias + cn);
            float v0 = (acc[mt][nt][0] * WSCALE_INV + b2.x) * scale;
            float v1 = (acc[mt][nt][1] * WSCALE_INV + b2.y) * scale;
            float v2 = (acc[mt][nt][2] * WSCALE_INV + b2.x) * scale;
            float v3 = (acc[mt][nt][3] * WSCALE_INV + b2.y) * scale;
            if (act) {
                v0 = gelu_exact(v0); v1 = gelu_exact(v1);
                v2 = gelu_exact(v2); v3 = gelu_exact(v3);
            }
            *(float2*)(C + (size_t)r0 * 256 + cn)       = make_float2(v0, v1);
            *(float2*)(C + (size_t)(r0 + 8) * 256 + cn) = make_float2(v2, v3);
        }
    }
}

// fused Q/K/V/PE: blockIdx.z selects
__global__ __launch_bounds__(256, 2) void gemm4(
    const float* __restrict__ bq, const float* __restrict__ bk,
    const float* __restrict__ bv, const float* __restrict__ p2b)
{
    const int z = blockIdx.z;
    const __half* Af = (z == 3) ? g_pe1 : g_af;
    const float* bias = (z == 0) ? bq : (z == 1) ? bk : (z == 2) ? bv : p2b;
    float* C = (z == 0) ? g_q : (z == 1) ? g_k : (z == 2) ? g_v : g_pe;
    float scale = (z == 0) ? 0.17677669529663689f : 1.f;
    gemm_core(Af, g_wh + (size_t)z * 65536, g_wl + (size_t)z * 65536,
              bias, C, scale, (z == 3) ? 1 : 0, blockIdx.x, blockIdx.y);
}
__global__ __launch_bounds__(256, 2) void gemm_out(const float* __restrict__ bo,
                                                   float* __restrict__ out)
{
    gemm_core(g_ctxf, g_wh + (size_t)4 * 65536, g_wl + (size_t)4 * 65536,
              bo, out, 1.f, 0, blockIdx.x, blockIdx.y);
}

// ================= windowed attention (tensor cores) =================
// S[i,j] = q_i·(k_j - pe_j) + (c·k_j - d·pe_j) + (q_i + d)·pe_i
// 128 threads, 4 warps x 16 rows. P stays in registers (S-accum == A-frag layout).
__global__ __launch_bounds__(128) void attn_k(
    const float* __restrict__ cvec, const float* __restrict__ dvec)
{
    const int w = blockIdx.x, h = blockIdx.y, b = blockIdx.z;

    __shared__ __half sq[64][40];
    __shared__ __half skw[64][40];
    __shared__ __half sv[64][40];
    __shared__ float sbias[64];
    __shared__ float su[64];

    const int t = threadIdx.x;
    const int tok = t >> 1;
    const int l = t & 1;
    const int dl = l * 16;

    // shifted -> original token index
    const int s = w * 64 + tok;
    const int o = s >> 4, r = s & 15;
    const int ic = ((o & 63) << 1) + (o >> 6);
    const int orig = ic * 16 + r;
    const size_t base = ((size_t)(b * SEQ + orig)) * 256 + h * 32 + dl;

    const float* cp = cvec + h * 32 + dl;
    const float* dp = dvec + h * 32 + dl;

    float bias_p = 0.f, u_p = 0.f;
#pragma unroll
    for (int i = 0; i < 16; i += 4) {
        float4 xq = *(const float4*)(g_q + base + i);
        float4 xk = *(const float4*)(g_k + base + i);
        float4 xv = *(const float4*)(g_v + base + i);
        float4 xp = *(const float4*)(g_pe + base + i);
        float4 xc = *(const float4*)(cp + i);
        float4 xd = *(const float4*)(dp + i);
        uint2 hq, hk, hv;
        hq.x = pkhf(xq.x, xq.y); hq.y = pkhf(xq.z, xq.w);
        hk.x = pkhf(xk.x - xp.x, xk.y - xp.y); hk.y = pkhf(xk.z - xp.z, xk.w - xp.w);
        hv.x = pkhf(xv.x, xv.y); hv.y = pkhf(xv.z, xv.w);
        *(uint2*)(&sq[tok][dl + i])  = hq;
        *(uint2*)(&skw[tok][dl + i]) = hk;
        *(uint2*)(&sv[tok][dl + i])  = hv;
        bias_p += xc.x * xk.x + xc.y * xk.y + xc.z * xk.z + xc.w * xk.w;
        bias_p -= xd.x * xp.x + xd.y * xp.y + xd.z * xp.z + xd.w * xp.w;
        u_p += (xq.x + xd.x) * xp.x + (xq.y + xd.y) * xp.y +
               (xq.z + xd.z) * xp.z + (xq.w + xd.w) * xp.w;
    }
    bias_p += __shfl_xor_sync(0xffffffffu, bias_p, 1);
    u_p    += __shfl_xor_sync(0xffffffffu, u_p, 1);
    if (l == 0) { sbias[tok] = bias_p; su[tok] = u_p; }
    __syncthreads();

    const int warp = t >> 5, lane = t & 31;
    const int la = lane & 15, lo8 = (lane >> 4) << 3;
    const int g = lane >> 2, q = lane & 3;
    const int r0 = warp * 16;

    // ---- S = q @ kw^T (16x64 per warp) ----
    float sacc[8][4];
#pragma unroll
    for (int j = 0; j < 8; j++)
#pragma unroll
        for (int i = 0; i < 4; i++) sacc[j][i] = 0.f;

#pragma unroll
    for (int ks = 0; ks < 2; ks++) {
        uint32_t a[4];
        ldsm4(a, &sq[r0 + la][ks * 16 + lo8]);
#pragma unroll
        for (int np = 0; np < 4; np++) {
            uint32_t bk[4];
            ldsm4(bk, &skw[np * 16 + la][ks * 16 + lo8]);
            // non-trans [n][k] load: k-half pairs are (0,2) and (1,3)
            mma_f16(sacc[2 * np],     a, bk[0], bk[2]);
            mma_f16(sacc[2 * np + 1], a, bk[1], bk[3]);
        }
    }

    // ---- bias + softmax (rows rg, rg+8 of this warp) ----
    const int rg = r0 + g;
    const float ug  = su[rg];
    const float ug8 = su[rg + 8];
    float m1 = -1e30f, m2 = -1e30f;
#pragma unroll
    for (int j = 0; j < 8; j++) {
        const int c0 = 8 * j + 2 * q;
        const float b0 = sbias[c0], b1 = sbias[c0 + 1];
        sacc[j][0] += ug  + b0; sacc[j][1] += ug  + b1;
        sacc[j][2] += ug8 + b0; sacc[j][3] += ug8 + b1;
        m1 = fmaxf(m1, fmaxf(sacc[j][0], sacc[j][1]));
        m2 = fmaxf(m2, fmaxf(sacc[j][2], sacc[j][3]));
    }
    m1 = fmaxf(m1, __shfl_xor_sync(0xffffffffu, m1, 1));
    m1 = fmaxf(m1, __shfl_xor_sync(0xffffffffu, m1, 2));
    m2 = fmaxf(m2, __shfl_xor_sync(0xffffffffu, m2, 1));
    m2 = fmaxf(m2, __shfl_xor_sync(0xffffffffu, m2, 2));

    float s1 = 0.f, s2 = 0.f;
    uint32_t pf[8], ph[8];
#pragma unroll
    for (int j = 0; j < 8; j++) {
        float e0 = __expf(sacc[j][0] - m1);
        float e1 = __expf(sacc[j][1] - m1);
        float e2 = __expf(sacc[j][2] - m2);
        float e3 = __expf(sacc[j][3] - m2);
        s1 += e0 + e1; s2 += e2 + e3;
        pf[j] = pkhf(e0, e1);
        ph[j] = pkhf(e2, e3);
    }
    s1 += __shfl_xor_sync(0xffffffffu, s1, 1);
    s1 += __shfl_xor_sync(0xffffffffu, s1, 2);
    s2 += __shfl_xor_sync(0xffffffffu, s2, 1);
    s2 += __shfl_xor_sync(0xffffffffu, s2, 2);
    const float inv1 = 1.f / s1;
    const float inv2 = 1.f / s2;

    // ---- O = P @ V : P consumed straight from registers ----
    float oacc[4][4];
#pragma unroll
    for (int j = 0; j < 4; j++)
#pragma unroll
        for (int i = 0; i < 4; i++) oacc[j][i] = 0.f;

#pragma unroll
    for (int kk = 0; kk < 4; kk++) {
        uint32_t a[4] = {pf[2 * kk], ph[2 * kk], pf[2 * kk + 1], ph[2 * kk + 1]};
#pragma unroll
        for (int np = 0; np < 2; np++) {
            uint32_t bv[4];
            ldsm4t(bv, &sv[kk * 16 + la][np * 16 + lo8]);
            // trans [k][n] load: k-half pairs are (0,1) and (2,3)  [R3-proven]
            mma_f16(oacc[2 * np],     a, bv[0], bv[1]);
            mma_f16(oacc[2 * np + 1], a, bv[2], bv[3]);
        }
    }

    // ---- scatter (rows rg, rg+8) ----
    {
        const int s_a = w * 64 + rg;
        const int oa_ = s_a >> 4, ra_ = s_a & 15;
        const int orig_a = (((oa_ & 63) << 1) + (oa_ >> 6)) * 16 + ra_;
        const size_t ba = ((size_t)(b * SEQ + orig_a)) * 256 + h * 32;
        const int s_b2 = w * 64 + rg + 8;
        const int ob_ = s_b2 >> 4, rb_ = s_b2 & 15;
        const int orig_b = (((ob_ & 63) << 1) + (ob_ >> 6)) * 16 + rb_;
        const size_t bb = ((size_t)(b * SEQ + orig_b)) * 256 + h * 32;
#pragma unroll
        for (int nt = 0; nt < 4; nt++) {
            const int d0 = 8 * nt + 2 * q;
            *(uint32_t*)(&g_ctxf[ba + d0]) = pkhf(oacc[nt][0] * inv1, oacc[nt][1] * inv1);
            *(uint32_t*)(&g_ctxf[bb + d0]) = pkhf(oacc[nt][2] * inv2, oacc[nt][3] * inv2);
        }
    }
}

// ================= launch =================
extern "C" void kernel_launch(void* const* d_in, const int* in_sizes, int n_in,
                              void* d_out, int out_size)
{
    const float* inputs = (const float*)d_in[0];
    const float* p      = (const float*)d_in[1];
    const float* wq     = (const float*)d_in[2];
    const float* bq     = (const float*)d_in[3];
    const float* wk     = (const float*)d_in[4];
    const float* bk     = (const float*)d_in[5];
    const float* wv     = (const float*)d_in[6];
    const float* bv     = (const float*)d_in[7];
    const float* wo     = (const float*)d_in[8];
    const float* bo     = (const float*)d_in[9];
    const float* p1w    = (const float*)d_in[10];
    const float* p1b    = (const float*)d_in[11];
    const float* p2w    = (const float*)d_in[12];
    const float* p2b    = (const float*)d_in[13];
    const float* lng    = (const float*)d_in[14];
    const float* lnb    = (const float*)d_in[15];
    const float* cv     = (const float*)d_in[16];
    const float* dv     = (const float*)d_in[17];
    float* out = (float*)d_out;

    cudaFuncSetAttribute(gemm4,    cudaFuncAttributeMaxDynamicSharedMemorySize, GSMEM);
    cudaFuncSetAttribute(gemm_out, cudaFuncAttributeMaxDynamicSharedMemorySize, GSMEM);

    prep_all<<<2129, 256>>>(wq, wk, wv, p2w, wo, inputs, p1w, p1b, lng);
    pos1_k<<<NTOK * 32 / 256, 256>>>(p, lnb);
    gemm4<<<dim3(64, 2, 4), 256, GSMEM>>>(bq, bk, bv, p2b);
    attn_k<<<dim3(NWIN, NHEAD, BATCH), 128>>>(cv, dv);
    gemm_out<<<dim3(64, 2), 256, GSMEM>>>(bo, out);
}